// round 7
// baseline (speedup 1.0000x reference)
#include <cuda_runtime.h>

#define T_LEN 8192
#define NF 26
#define NTILES 16384            // 64 batches x 256 tiles of 32 steps
#define WARPS 16
#define NTHREADS 512
#define NBLOCKS (NTILES / (WARPS * 2))   // 512: exactly 2 tiles per warp
#define STRIDE 36               // floats per staged row: 16B-aligned, conflict-free
#define FMASK 0x03FFFFFFu
#define WARM 8

#define XS_FLOATS (NF * STRIDE)                    // 936
#define SMEM_XS_BYTES (WARPS * XS_FLOATS * 4)      // 59904
#define SMEM_TBL_OFF  SMEM_XS_BYTES
#define SMEM_A_OFF   (SMEM_TBL_OFF + 3 * 4 * 128 * 8)
#define SMEM_C_OFF   (SMEM_A_OFF + 3 * 2 * NF * 4)
#define SMEM_TOTAL   (SMEM_C_OFF + 8)

// 0xFFFFFFFF if a > b else 0 (FSET: register mask, no predicate)
__device__ __forceinline__ unsigned fset_gt(float a, float b) {
    unsigned r;
    asm("set.gt.u32.f32 %0, %1, %2;" : "=r"(r) : "f"(a), "f"(b));
    return r;
}
__device__ __forceinline__ float andn_f(float w, unsigned k) {
    return __uint_as_float(__float_as_uint(w) & ~k);
}

// 32x32 bit-matrix transpose across the warp: lane r bit c -> lane c bit r.
// Per stage: keep own bits under KM, take PARTNER bits under KM, rotate them
// into the complementary positions (lo: rotl s, hi: rotr s).
__device__ __forceinline__ unsigned bitT(unsigned m, int lane) {
    #pragma unroll
    for (int i = 0; i < 5; i++) {
        const int s = 1 << i;
        const unsigned L = (i == 0) ? 0x55555555u : (i == 1) ? 0x33333333u :
                           (i == 2) ? 0x0F0F0F0Fu : (i == 3) ? 0x00FF00FFu : 0x0000FFFFu;
        const bool hi     = (lane & s) != 0;
        const unsigned KM = hi ? ~L : L;          // bits this lane keeps
        const unsigned r  = hi ? (32 - s) : s;    // rotl amount for incoming bits
        const unsigned o  = __shfl_xor_sync(0xffffffffu, m, s);
        unsigned t = o & KM;                      // FIX: partner's kept-half moves to us
        t = __funnelshift_l(t, t, r);             // rotl(t, r) -> complementary positions
        m = (m & KM) | t;
    }
    return m;
}

// rescaled LIF step: w' = (1-a)w + x ; spike w' > vth/a ; reset via bit-AND
#define STEPW(xv) do {                                             \
    w0 = fmaf(c0, w0, (xv)); w0 = andn_f(w0, fset_gt(w0, TH0));    \
    w1 = fmaf(c1, w1, (xv)); w1 = andn_f(w1, fset_gt(w1, TH1));    \
    w2 = fmaf(c2, w2, (xv)); w2 = andn_f(w2, fset_gt(w2, TH2));    \
} while (0)

#define STEP(xv, JJ) do {                                          \
    w0 = fmaf(c0, w0, (xv));                                       \
    w1 = fmaf(c1, w1, (xv));                                       \
    w2 = fmaf(c2, w2, (xv));                                       \
    const unsigned k0 = fset_gt(w0, TH0);                          \
    const unsigned k1 = fset_gt(w1, TH1);                          \
    const unsigned k2 = fset_gt(w2, TH2);                          \
    w0 = andn_f(w0, k0); m0 |= k0 & (1u << (JJ));                  \
    w1 = andn_f(w1, k1); m1 |= k1 & (1u << (JJ));                  \
    w2 = andn_f(w2, k2); m2 |= k2 & (1u << (JJ));                  \
} while (0)

__global__ __launch_bounds__(NTHREADS, 3)
void snn_kernel(const float* __restrict__ inp,
                const float* __restrict__ tau,
                const float* __restrict__ vth,
                const float* __restrict__ conv_w,
                const float* __restrict__ conv_b,
                const float* __restrict__ w1p, const float* __restrict__ b1,
                const float* __restrict__ w2p, const float* __restrict__ b2,
                const float* __restrict__ w3p, const float* __restrict__ b3,
                float* __restrict__ out)
{
    extern __shared__ char smem[];
    float*  xs    = (float*)smem;                       // [WARPS][936]
    float2* tbl   = (float2*)(smem + SMEM_TBL_OFF);     // [3][4][128]
    float*  A_sh  = (float*)(smem + SMEM_A_OFF);        // [3][2][NF]
    float*  C_sh  = (float*)(smem + SMEM_C_OFF);

    const int tid  = threadIdx.x;
    const int warp = tid >> 5;
    const int lane = tid & 31;

    // ---- fold weights: A[c][k][f] = (w3@w2@w1)[k][f]*conv_w[c]; C[k] = folded biases ----
    if (tid < 52) {
        const int k = tid / NF, f = tid % NF;
        float w32[12];
        #pragma unroll
        for (int j = 0; j < 12; j++) {
            float s = 0.f;
            #pragma unroll
            for (int i = 0; i < 4; i++) s += w3p[k * 4 + i] * w2p[i * 12 + j];
            w32[j] = s;
        }
        float wf = 0.f;
        #pragma unroll
        for (int j = 0; j < 12; j++) wf += w32[j] * w1p[j * NF + f];
        #pragma unroll
        for (int c = 0; c < 3; c++) A_sh[(c * 2 + k) * NF + f] = wf * conv_w[c];
    }
    if (tid >= 52 && tid < 54) {
        const int k = tid - 52;
        float bt = b3[k];
        for (int i = 0; i < 4; i++) {
            float t2 = b2[i];
            for (int j = 0; j < 12; j++) t2 += w2p[i * 12 + j] * b1[j];
            bt += w3p[k * 4 + i] * t2;
        }
        float sw = 0.f;
        for (int j = 0; j < 12; j++) {
            float s = 0.f;
            for (int i = 0; i < 4; i++) s += w3p[k * 4 + i] * w2p[i * 12 + j];
            float rowsum = 0.f;
            for (int f = 0; f < NF; f++) rowsum += w1p[j * NF + f];
            sw += s * rowsum;
        }
        C_sh[k] = conv_b[0] * sw + bt;
    }
    __syncthreads();

    // ---- 7-bit lookup tables: tbl[c][ch][mask] = (sum A[c][0][f], sum A[c][1][f]) ----
    for (int e = tid; e < 3 * 4 * 128; e += NTHREADS) {
        const int c  = e >> 9;
        const int ch = (e >> 7) & 3;
        const int m  = e & 127;
        float s0 = 0.f, s1 = 0.f;
        #pragma unroll
        for (int b = 0; b < 7; b++) {
            const int f = ch * 7 + b;
            if (((m >> b) & 1) && f < NF) {
                s0 += A_sh[(c * 2 + 0) * NF + f];
                s1 += A_sh[(c * 2 + 1) * NF + f];
            }
        }
        tbl[(c * 4 + ch) * 128 + m] = make_float2(s0, s1);
    }
    __syncthreads();

    // ---- scan: each warp owns exactly 2 contiguous tiles of one batch ----
    const int g     = blockIdx.x * WARPS + warp;
    const int tile0 = g * 2;
    const int b     = tile0 >> 8;
    const int tb0   = tile0 & 255;

    const float* ib = inp + (size_t)b * NF * T_LEN;
    float*       ob = out + (size_t)b * 2 * T_LEN;

    const float a0 = 0.001f * tau[0], a1 = 0.001f * tau[1], a2 = 0.001f * tau[2];
    const float c0 = 1.f - a0, c1 = 1.f - a1, c2 = 1.f - a2;
    const float TH0 = vth[0] / a0, TH1 = vth[1] / a1, TH2 = vth[2] / a2;
    const float C0 = C_sh[0], C1 = C_sh[1];

    float* xw = xs + warp * XS_FLOATS;
    const float* xrow = xw + (lane < NF ? lane : NF - 1) * STRIDE;
    const int fq = lane >> 3;           // staging: row within quad-group
    const int cq = (lane & 7) << 2;     // staging: column (float4)

    float w0 = 0.f, w1 = 0.f, w2 = 0.f;

    // 8-step warm-up (skipped at batch start; converges exactly w.p. 1-7e-13/chain)
    if (tb0 != 0) {
        const int tw = tb0 * 32 - WARM;
        if (lane < WARM) {
            #pragma unroll
            for (int f = 0; f < NF; f++)
                xw[f * STRIDE + lane] = ib[(size_t)f * T_LEN + tw + lane];
        }
        __syncwarp();
        {
            const float4 xa = *(const float4*)(xrow + 0);
            const float4 xb = *(const float4*)(xrow + 4);
            STEPW(xa.x); STEPW(xa.y); STEPW(xa.z); STEPW(xa.w);
            STEPW(xb.x); STEPW(xb.y); STEPW(xb.z); STEPW(xb.w);
        }
        __syncwarp();
    }

    #pragma unroll 1
    for (int tt = 0; tt < 2; tt++) {
        const int t0 = (tb0 + tt) * 32;

        // stage tile: LDG.128 -> STS.128, each 8-lane phase = one contiguous 144B row
        #pragma unroll
        for (int i = 0; i < 7; i++) {
            const int f = i * 4 + fq;
            if (f < NF) {
                const float4 v = *(const float4*)(ib + (size_t)f * T_LEN + t0 + cq);
                *(float4*)(xw + f * STRIDE + cq) = v;
            }
        }
        __syncwarp();

        unsigned m0 = 0, m1 = 0, m2 = 0;
        #pragma unroll
        for (int jb = 0; jb < 32; jb += 4) {
            const float4 xv = *(const float4*)(xrow + jb);
            STEP(xv.x, jb + 0);
            STEP(xv.y, jb + 1);
            STEP(xv.z, jb + 2);
            STEP(xv.w, jb + 3);
        }
        __syncwarp();

        // transpose: lane f holds time-mask -> lane t holds feature-mask
        m0 = bitT(m0, lane) & FMASK;
        m1 = bitT(m1, lane) & FMASK;
        m2 = bitT(m2, lane) & FMASK;

        float o0 = C0, o1 = C1;
        #pragma unroll
        for (int ch = 0; ch < 4; ch++) {
            const float2 e0 = tbl[(0 * 4 + ch) * 128 + ((m0 >> (7 * ch)) & 127)];
            const float2 e1 = tbl[(1 * 4 + ch) * 128 + ((m1 >> (7 * ch)) & 127)];
            const float2 e2 = tbl[(2 * 4 + ch) * 128 + ((m2 >> (7 * ch)) & 127)];
            o0 += e0.x + e1.x + e2.x;
            o1 += e0.y + e1.y + e2.y;
        }
        const int t = t0 + lane;
        ob[t]         = o0;
        ob[T_LEN + t] = o1;
    }
}

extern "C" void kernel_launch(void* const* d_in, const int* in_sizes, int n_in,
                              void* d_out, int out_size) {
    const float* inputs = (const float*)d_in[0];
    const float* tau    = (const float*)d_in[1];
    const float* vth    = (const float*)d_in[2];
    const float* conv_w = (const float*)d_in[3];
    const float* conv_b = (const float*)d_in[4];
    const float* w1     = (const float*)d_in[5];
    const float* b1     = (const float*)d_in[6];
    const float* w2     = (const float*)d_in[7];
    const float* b2     = (const float*)d_in[8];
    const float* w3     = (const float*)d_in[9];
    const float* b3     = (const float*)d_in[10];

    cudaFuncSetAttribute(snn_kernel, cudaFuncAttributeMaxDynamicSharedMemorySize,
                         SMEM_TOTAL);
    snn_kernel<<<NBLOCKS, NTHREADS, SMEM_TOTAL>>>(
        inputs, tau, vth, conv_w, conv_b, w1, b1, w2, b2, w3, b3, (float*)d_out);
}

// round 8
// speedup vs baseline: 1.0570x; 1.0570x over previous
#include <cuda_runtime.h>

#define T_LEN 8192
#define NF 26
#define NTILES 16384            // 64 batches x 256 tiles of 32 steps
#define WARPS 8
#define NTHREADS 256
#define NBLOCKS 740             // 148 SMs x 5 blocks = exactly one wave
#define GWARPS (NBLOCKS * WARPS)   // 5920 -> 2..3 tiles per warp
#define STRIDE 36               // floats per staged row: 16B-aligned, conflict-free
#define FMASK 0x03FFFFFFu
#define WARM 8

#define XS_FLOATS (NF * STRIDE)   // 936 floats = 3744 B per warp

// 0xFFFFFFFF if a > b else 0 (FSET: register mask, no predicate)
__device__ __forceinline__ unsigned fset_gt(float a, float b) {
    unsigned r;
    asm("set.gt.u32.f32 %0, %1, %2;" : "=r"(r) : "f"(a), "f"(b));
    return r;
}
__device__ __forceinline__ float andn_f(float w, unsigned k) {
    return __uint_as_float(__float_as_uint(w) & ~k);
}

// 32x32 bit-matrix transpose across the warp: lane r bit c -> lane c bit r.
__device__ __forceinline__ unsigned bitT(unsigned m, int lane) {
    #pragma unroll
    for (int i = 0; i < 5; i++) {
        const int s = 1 << i;
        const unsigned L = (i == 0) ? 0x55555555u : (i == 1) ? 0x33333333u :
                           (i == 2) ? 0x0F0F0F0Fu : (i == 3) ? 0x00FF00FFu : 0x0000FFFFu;
        const bool hi     = (lane & s) != 0;
        const unsigned KM = hi ? ~L : L;          // bits this lane keeps
        const unsigned r  = hi ? (32 - s) : s;    // rotl amount for incoming bits
        const unsigned o  = __shfl_xor_sync(0xffffffffu, m, s);
        unsigned t = o & KM;                      // partner's kept-half moves to us
        t = __funnelshift_l(t, t, r);
        m = (m & KM) | t;
    }
    return m;
}

// rescaled LIF step: w' = (1-a)w + x ; spike w' > vth/a ; reset via bit-AND
#define STEPW(xv) do {                                             \
    w0 = fmaf(c0, w0, (xv)); w0 = andn_f(w0, fset_gt(w0, TH0));    \
    w1 = fmaf(c1, w1, (xv)); w1 = andn_f(w1, fset_gt(w1, TH1));    \
    w2 = fmaf(c2, w2, (xv)); w2 = andn_f(w2, fset_gt(w2, TH2));    \
} while (0)

#define STEP(xv, JJ) do {                                          \
    w0 = fmaf(c0, w0, (xv));                                       \
    w1 = fmaf(c1, w1, (xv));                                       \
    w2 = fmaf(c2, w2, (xv));                                       \
    const unsigned k0 = fset_gt(w0, TH0);                          \
    const unsigned k1 = fset_gt(w1, TH1);                          \
    const unsigned k2 = fset_gt(w2, TH2);                          \
    w0 = andn_f(w0, k0); m0 |= k0 & (1u << (JJ));                  \
    w1 = andn_f(w1, k1); m1 |= k1 & (1u << (JJ));                  \
    w2 = andn_f(w2, k2); m2 |= k2 & (1u << (JJ));                  \
} while (0)

__global__ __launch_bounds__(NTHREADS, 5)
void snn_kernel(const float* __restrict__ inp,
                const float* __restrict__ tau,
                const float* __restrict__ vth,
                const float* __restrict__ conv_w,
                const float* __restrict__ conv_b,
                const float* __restrict__ w1p, const float* __restrict__ b1,
                const float* __restrict__ w2p, const float* __restrict__ b2,
                const float* __restrict__ w3p, const float* __restrict__ b3,
                float* __restrict__ out)
{
    __shared__ __align__(16) float xs[WARPS][XS_FLOATS];  // staged input tiles
    __shared__ float2 tbl[3][4][128];                     // [pop][7b chunk][mask]
    __shared__ float  A_sh[3][2][NF];
    __shared__ float  C_sh[2];

    const int tid  = threadIdx.x;
    const int warp = tid >> 5;
    const int lane = tid & 31;

    // ---- fold weights: A[c][k][f] = (w3@w2@w1)[k][f]*conv_w[c]; C[k] = folded biases ----
    if (tid < 52) {
        const int k = tid / NF, f = tid % NF;
        float w32[12];
        #pragma unroll
        for (int j = 0; j < 12; j++) {
            float s = 0.f;
            #pragma unroll
            for (int i = 0; i < 4; i++) s += w3p[k * 4 + i] * w2p[i * 12 + j];
            w32[j] = s;
        }
        float wf = 0.f;
        #pragma unroll
        for (int j = 0; j < 12; j++) wf += w32[j] * w1p[j * NF + f];
        #pragma unroll
        for (int c = 0; c < 3; c++) A_sh[c][k][f] = wf * conv_w[c];
    }
    if (tid >= 52 && tid < 54) {
        const int k = tid - 52;
        float bt = b3[k];
        for (int i = 0; i < 4; i++) {
            float t2 = b2[i];
            for (int j = 0; j < 12; j++) t2 += w2p[i * 12 + j] * b1[j];
            bt += w3p[k * 4 + i] * t2;
        }
        float sw = 0.f;
        for (int j = 0; j < 12; j++) {
            float s = 0.f;
            for (int i = 0; i < 4; i++) s += w3p[k * 4 + i] * w2p[i * 12 + j];
            float rowsum = 0.f;
            for (int f = 0; f < NF; f++) rowsum += w1p[j * NF + f];
            sw += s * rowsum;
        }
        C_sh[k] = conv_b[0] * sw + bt;
    }
    __syncthreads();

    // ---- 7-bit lookup tables ----
    for (int e = tid; e < 3 * 4 * 128; e += NTHREADS) {
        const int c  = e >> 9;
        const int ch = (e >> 7) & 3;
        const int m  = e & 127;
        float s0 = 0.f, s1 = 0.f;
        #pragma unroll
        for (int b = 0; b < 7; b++) {
            const int f = ch * 7 + b;
            if (((m >> b) & 1) && f < NF) { s0 += A_sh[c][0][f]; s1 += A_sh[c][1][f]; }
        }
        tbl[c][ch][m] = make_float2(s0, s1);
    }
    __syncthreads();

    // ---- contiguous tile ranges, exactly one wave ----
    const int g  = blockIdx.x * WARPS + warp;
    const int ts = (int)(((long long)g * NTILES) / GWARPS);
    const int te = (int)(((long long)(g + 1) * NTILES) / GWARPS);

    const float a0 = 0.001f * tau[0], a1 = 0.001f * tau[1], a2 = 0.001f * tau[2];
    const float c0 = 1.f - a0, c1 = 1.f - a1, c2 = 1.f - a2;
    const float TH0 = vth[0] / a0, TH1 = vth[1] / a1, TH2 = vth[2] / a2;
    const float C0 = C_sh[0], C1 = C_sh[1];

    float* xw = xs[warp];
    const float4* xr4 = (const float4*)(xw + (lane < NF ? lane : NF - 1) * STRIDE);
    const int fq = lane >> 3;           // staging: feature sub-row
    const int cq = (lane & 7) << 2;     // staging: column (float4)

    float w0 = 0.f, w1 = 0.f, w2 = 0.f;

    #pragma unroll 1
    for (int tile = ts; tile < te; tile++) {
        const int b  = tile >> 8;
        const int tb = tile & 255;
        const int t0 = tb << 5;
        const float* ib = inp + (size_t)b * NF * T_LEN;

        if (tb == 0) {
            w0 = w1 = w2 = 0.f;                 // exact batch start
        } else if (tile == ts) {
            // 8-step warm-up: converges exactly w.p. 1-7e-13 per chain
            if (lane < WARM) {
                #pragma unroll
                for (int f = 0; f < NF; f++)
                    xw[f * STRIDE + lane] = ib[(size_t)f * T_LEN + t0 - WARM + lane];
            }
            __syncwarp();
            const float4 xa = xr4[0];
            const float4 xb = xr4[1];
            STEPW(xa.x); STEPW(xa.y); STEPW(xa.z); STEPW(xa.w);
            STEPW(xb.x); STEPW(xb.y); STEPW(xb.z); STEPW(xb.w);
            __syncwarp();
        }

        // stage tile: LDG.128 -> STS.128, 8-lane phase = one contiguous 144B row
        #pragma unroll
        for (int i = 0; i < 7; i++) {
            const int f = i * 4 + fq;
            if (f < NF) {
                const float4 v = *(const float4*)(ib + (size_t)f * T_LEN + t0 + cq);
                *(float4*)(xw + f * STRIDE + cq) = v;
            }
        }
        __syncwarp();

        // scan with register double-buffered x (LDS off the critical path)
        unsigned m0 = 0, m1 = 0, m2 = 0;
        float4 xa = xr4[0];
        #pragma unroll
        for (int q = 0; q < 8; q++) {
            const float4 xn = (q < 7) ? xr4[q + 1] : xa;
            STEP(xa.x, q * 4 + 0);
            STEP(xa.y, q * 4 + 1);
            STEP(xa.z, q * 4 + 2);
            STEP(xa.w, q * 4 + 3);
            xa = xn;
        }
        __syncwarp();

        // transpose: lane f holds time-mask -> lane t holds feature-mask
        m0 = bitT(m0, lane) & FMASK;
        m1 = bitT(m1, lane) & FMASK;
        m2 = bitT(m2, lane) & FMASK;

        float o0 = C0, o1 = C1;
        #pragma unroll
        for (int ch = 0; ch < 4; ch++) {
            const float2 e0 = tbl[0][ch][(m0 >> (7 * ch)) & 127];
            const float2 e1 = tbl[1][ch][(m1 >> (7 * ch)) & 127];
            const float2 e2 = tbl[2][ch][(m2 >> (7 * ch)) & 127];
            o0 += e0.x + e1.x + e2.x;
            o1 += e0.y + e1.y + e2.y;
        }
        float* ob = out + (size_t)b * 2 * T_LEN;
        const int t = t0 + lane;
        ob[t]         = o0;
        ob[T_LEN + t] = o1;
    }
}

extern "C" void kernel_launch(void* const* d_in, const int* in_sizes, int n_in,
                              void* d_out, int out_size) {
    const float* inputs = (const float*)d_in[0];
    const float* tau    = (const float*)d_in[1];
    const float* vth    = (const float*)d_in[2];
    const float* conv_w = (const float*)d_in[3];
    const float* conv_b = (const float*)d_in[4];
    const float* w1     = (const float*)d_in[5];
    const float* b1     = (const float*)d_in[6];
    const float* w2     = (const float*)d_in[7];
    const float* b2     = (const float*)d_in[8];
    const float* w3     = (const float*)d_in[9];
    const float* b3     = (const float*)d_in[10];

    snn_kernel<<<NBLOCKS, NTHREADS>>>(
        inputs, tau, vth, conv_w, conv_b, w1, b1, w2, b2, w3, b3, (float*)d_out);
}

// round 9
// speedup vs baseline: 1.2252x; 1.1592x over previous
#include <cuda_runtime.h>

#define T_LEN 8192
#define NF 26
#define NTILES 16384            // 64 batches x 256 tiles of 32 steps
#define WARPS 8
#define NTHREADS 256
#define NBLOCKS 444             // 148 SMs x 3 blocks = exactly one wave
#define GWARPS (NBLOCKS * WARPS)   // 3552 -> 4..5 tiles per warp
#define STRIDE 36               // floats per staged row: 16B-aligned, conflict-free
#define FMASK 0x03FFFFFFu
#define WARM 8

#define XS_FLOATS (NF * STRIDE)                 // 936 floats = 3744 B / warp / buf
#define XS_BYTES  (2 * WARPS * XS_FLOATS * 4)   // 59904 (double-buffered)
#define TBL_OFF   XS_BYTES
#define A_OFF     (TBL_OFF + 3 * 4 * 128 * 8)   // 72192
#define C_OFF     (A_OFF + 3 * 2 * NF * 4)      // 72816
#define SMEM_TOTAL (C_OFF + 8)                  // 72824

__device__ __forceinline__ unsigned fset_gt(float a, float b) {
    unsigned r;
    asm("set.gt.u32.f32 %0, %1, %2;" : "=r"(r) : "f"(a), "f"(b));
    return r;
}
__device__ __forceinline__ float andn_f(float w, unsigned k) {
    return __uint_as_float(__float_as_uint(w) & ~k);
}
__device__ __forceinline__ void cp16(unsigned s, const void* g) {
    asm volatile("cp.async.cg.shared.global [%0], [%1], 16;" :: "r"(s), "l"(g));
}
#define CP_COMMIT() asm volatile("cp.async.commit_group;" ::: "memory")
#define CP_WAIT1()  asm volatile("cp.async.wait_group 1;" ::: "memory")

// 32x32 bit-matrix transpose across the warp: lane r bit c -> lane c bit r.
__device__ __forceinline__ unsigned bitT(unsigned m, int lane) {
    #pragma unroll
    for (int i = 0; i < 5; i++) {
        const int s = 1 << i;
        const unsigned L = (i == 0) ? 0x55555555u : (i == 1) ? 0x33333333u :
                           (i == 2) ? 0x0F0F0F0Fu : (i == 3) ? 0x00FF00FFu : 0x0000FFFFu;
        const bool hi     = (lane & s) != 0;
        const unsigned KM = hi ? ~L : L;
        const unsigned r  = hi ? (32 - s) : s;
        const unsigned o  = __shfl_xor_sync(0xffffffffu, m, s);
        unsigned t = o & KM;
        t = __funnelshift_l(t, t, r);
        m = (m & KM) | t;
    }
    return m;
}

// rescaled LIF step: w' = (1-a)w + x ; spike w' > vth/a ; reset via bit-AND
#define STEPW(xv) do {                                             \
    w0 = fmaf(c0, w0, (xv)); w0 = andn_f(w0, fset_gt(w0, TH0));    \
    w1 = fmaf(c1, w1, (xv)); w1 = andn_f(w1, fset_gt(w1, TH1));    \
    w2 = fmaf(c2, w2, (xv)); w2 = andn_f(w2, fset_gt(w2, TH2));    \
} while (0)

#define STEP(xv, JJ) do {                                          \
    w0 = fmaf(c0, w0, (xv));                                       \
    w1 = fmaf(c1, w1, (xv));                                       \
    w2 = fmaf(c2, w2, (xv));                                       \
    const unsigned k0 = fset_gt(w0, TH0);                          \
    const unsigned k1 = fset_gt(w1, TH1);                          \
    const unsigned k2 = fset_gt(w2, TH2);                          \
    w0 = andn_f(w0, k0); m0 |= k0 & (1u << (JJ));                  \
    w1 = andn_f(w1, k1); m1 |= k1 & (1u << (JJ));                  \
    w2 = andn_f(w2, k2); m2 |= k2 & (1u << (JJ));                  \
} while (0)

__global__ __launch_bounds__(NTHREADS, 3)
void snn_kernel(const float* __restrict__ inp,
                const float* __restrict__ tau,
                const float* __restrict__ vth,
                const float* __restrict__ conv_w,
                const float* __restrict__ conv_b,
                const float* __restrict__ w1p, const float* __restrict__ b1,
                const float* __restrict__ w2p, const float* __restrict__ b2,
                const float* __restrict__ w3p, const float* __restrict__ b3,
                float* __restrict__ out)
{
    extern __shared__ __align__(16) char smem[];
    float*  xs   = (float*)smem;                   // [2][WARPS][XS_FLOATS]
    float2* tbl  = (float2*)(smem + TBL_OFF);      // [3][4][128]
    float*  A_sh = (float*)(smem + A_OFF);         // [3][2][NF]
    float*  C_sh = (float*)(smem + C_OFF);

    const int tid  = threadIdx.x;
    const int warp = tid >> 5;
    const int lane = tid & 31;

    // ---- fold weights: A[c][k][f] = (w3@w2@w1)[k][f]*conv_w[c]; C[k] = folded biases ----
    if (tid < 52) {
        const int k = tid / NF, f = tid % NF;
        float w32[12];
        #pragma unroll
        for (int j = 0; j < 12; j++) {
            float s = 0.f;
            #pragma unroll
            for (int i = 0; i < 4; i++) s += w3p[k * 4 + i] * w2p[i * 12 + j];
            w32[j] = s;
        }
        float wf = 0.f;
        #pragma unroll
        for (int j = 0; j < 12; j++) wf += w32[j] * w1p[j * NF + f];
        #pragma unroll
        for (int c = 0; c < 3; c++) A_sh[(c * 2 + k) * NF + f] = wf * conv_w[c];
    }
    if (tid >= 52 && tid < 54) {
        const int k = tid - 52;
        float bt = b3[k];
        for (int i = 0; i < 4; i++) {
            float t2 = b2[i];
            for (int j = 0; j < 12; j++) t2 += w2p[i * 12 + j] * b1[j];
            bt += w3p[k * 4 + i] * t2;
        }
        float sw = 0.f;
        for (int j = 0; j < 12; j++) {
            float s = 0.f;
            for (int i = 0; i < 4; i++) s += w3p[k * 4 + i] * w2p[i * 12 + j];
            float rowsum = 0.f;
            for (int f = 0; f < NF; f++) rowsum += w1p[j * NF + f];
            sw += s * rowsum;
        }
        C_sh[k] = conv_b[0] * sw + bt;
    }
    __syncthreads();

    // ---- 7-bit lookup tables ----
    for (int e = tid; e < 3 * 4 * 128; e += NTHREADS) {
        const int c  = e >> 9;
        const int ch = (e >> 7) & 3;
        const int m  = e & 127;
        float s0 = 0.f, s1 = 0.f;
        #pragma unroll
        for (int b = 0; b < 7; b++) {
            const int f = ch * 7 + b;
            if (((m >> b) & 1) && f < NF) {
                s0 += A_sh[(c * 2 + 0) * NF + f];
                s1 += A_sh[(c * 2 + 1) * NF + f];
            }
        }
        tbl[(c * 4 + ch) * 128 + m] = make_float2(s0, s1);
    }
    __syncthreads();

    // ---- contiguous tile ranges, one wave, cp.async double-buffered ----
    const int g  = blockIdx.x * WARPS + warp;
    const int ts = (int)(((long long)g * NTILES) / GWARPS);
    const int te = (int)(((long long)(g + 1) * NTILES) / GWARPS);

    const float a0 = 0.001f * tau[0], a1 = 0.001f * tau[1], a2 = 0.001f * tau[2];
    const float c0 = 1.f - a0, c1 = 1.f - a1, c2 = 1.f - a2;
    const float TH0 = vth[0] / a0, TH1 = vth[1] / a1, TH2 = vth[2] / a2;
    const float C0 = C_sh[0], C1 = C_sh[1];

    float* bufp[2] = { xs + warp * XS_FLOATS, xs + (WARPS + warp) * XS_FLOATS };
    const unsigned bufs0 = (unsigned)__cvta_generic_to_shared(bufp[0]);
    const unsigned bufs1 = (unsigned)__cvta_generic_to_shared(bufp[1]);
    const int row = (lane < NF ? lane : NF - 1) * STRIDE;
    const int fq = lane >> 3;           // staging: feature sub-row
    const int cq = (lane & 7) << 2;     // staging: column (float4)

    float w0 = 0.f, w1 = 0.f, w2 = 0.f;

    // 8-step warm-up at range start (plain LDG/STS into buf0, consumed before pipeline)
    {
        const int tb0 = ts & 255;
        if (tb0 != 0) {
            const float* ib = inp + (size_t)(ts >> 8) * NF * T_LEN;
            const int tw = tb0 * 32 - WARM;
            if (lane < WARM) {
                #pragma unroll
                for (int f = 0; f < NF; f++)
                    bufp[0][f * STRIDE + lane] = ib[(size_t)f * T_LEN + tw + lane];
            }
            __syncwarp();
            const float4* xr = (const float4*)(bufp[0] + row);
            const float4 xa = xr[0];
            const float4 xb = xr[1];
            STEPW(xa.x); STEPW(xa.y); STEPW(xa.z); STEPW(xa.w);
            STEPW(xb.x); STEPW(xb.y); STEPW(xb.z); STEPW(xb.w);
            __syncwarp();
        }
    }

    // prologue: async-issue tile ts into buf0
    {
        const float* ib = inp + (size_t)(ts >> 8) * NF * T_LEN + ((ts & 255) << 5);
        #pragma unroll
        for (int i = 0; i < 7; i++) {
            const int f = i * 4 + fq;
            if (f < NF) cp16(bufs0 + (unsigned)(f * STRIDE + cq) * 4,
                             ib + (size_t)f * T_LEN + cq);
        }
        CP_COMMIT();
    }

    int cur = 0;
    #pragma unroll 1
    for (int tile = ts; tile < te; tile++) {
        // prefetch next tile into the other buffer (empty commit on last iter)
        if (tile + 1 < te) {
            const int bn  = (tile + 1) >> 8;
            const int t0n = ((tile + 1) & 255) << 5;
            const float* ibn = inp + (size_t)bn * NF * T_LEN + t0n;
            const unsigned dst = cur ? bufs0 : bufs1;
            #pragma unroll
            for (int i = 0; i < 7; i++) {
                const int f = i * 4 + fq;
                if (f < NF) cp16(dst + (unsigned)(f * STRIDE + cq) * 4,
                                 ibn + (size_t)f * T_LEN + cq);
            }
        }
        CP_COMMIT();
        CP_WAIT1();              // oldest (current tile's) group complete
        __syncwarp();

        const int b  = tile >> 8;
        const int tb = tile & 255;
        const int t0 = tb << 5;
        if (tb == 0) { w0 = w1 = w2 = 0.f; }   // exact batch start

        const float4* xr4 = (const float4*)(bufp[cur] + row);
        unsigned m0 = 0, m1 = 0, m2 = 0;
        float4 xa = xr4[0];
        #pragma unroll
        for (int q = 0; q < 8; q++) {
            const float4 xn = (q < 7) ? xr4[q + 1] : xa;
            STEP(xa.x, q * 4 + 0);
            STEP(xa.y, q * 4 + 1);
            STEP(xa.z, q * 4 + 2);
            STEP(xa.w, q * 4 + 3);
            xa = xn;
        }

        // transpose: lane f holds time-mask -> lane t holds feature-mask
        m0 = bitT(m0, lane) & FMASK;
        m1 = bitT(m1, lane) & FMASK;
        m2 = bitT(m2, lane) & FMASK;

        float o0 = C0, o1 = C1;
        #pragma unroll
        for (int ch = 0; ch < 4; ch++) {
            const float2 e0 = tbl[(0 * 4 + ch) * 128 + ((m0 >> (7 * ch)) & 127)];
            const float2 e1 = tbl[(1 * 4 + ch) * 128 + ((m1 >> (7 * ch)) & 127)];
            const float2 e2 = tbl[(2 * 4 + ch) * 128 + ((m2 >> (7 * ch)) & 127)];
            o0 += e0.x + e1.x + e2.x;
            o1 += e0.y + e1.y + e2.y;
        }
        float* ob = out + (size_t)b * 2 * T_LEN;
        const int t = t0 + lane;
        ob[t]         = o0;
        ob[T_LEN + t] = o1;

        cur ^= 1;
    }
}

extern "C" void kernel_launch(void* const* d_in, const int* in_sizes, int n_in,
                              void* d_out, int out_size) {
    const float* inputs = (const float*)d_in[0];
    const float* tau    = (const float*)d_in[1];
    const float* vth    = (const float*)d_in[2];
    const float* conv_w = (const float*)d_in[3];
    const float* conv_b = (const float*)d_in[4];
    const float* w1     = (const float*)d_in[5];
    const float* b1     = (const float*)d_in[6];
    const float* w2     = (const float*)d_in[7];
    const float* b2     = (const float*)d_in[8];
    const float* w3     = (const float*)d_in[9];
    const float* b3     = (const float*)d_in[10];

    cudaFuncSetAttribute(snn_kernel, cudaFuncAttributeMaxDynamicSharedMemorySize,
                         SMEM_TOTAL);
    snn_kernel<<<NBLOCKS, NTHREADS, SMEM_TOTAL>>>(
        inputs, tau, vth, conv_w, conv_b, w1, b1, w2, b2, w3, b3, (float*)d_out);
}